// round 1
// baseline (speedup 1.0000x reference)
#include <cuda_runtime.h>

// Problem constants
#define NN 8192          // nodes
#define DIN 512
#define DOUT 64
#define HEADS 8
#define MWORDS 256       // 8192/32 mask words per row

// Scratch (device globals — no runtime allocation allowed)
__device__ float    g_Wh[NN * 512];          // [N][H*64] fp32, 16 MB
__device__ float    g_f1[HEADS * NN];
__device__ float    g_f2[HEADS * NN];
__device__ unsigned g_mask[NN * MWORDS];     // 8 MB bitmask

// ---------------- packed f32x2 helpers (Blackwell FFMA2 path) ----------------
__device__ __forceinline__ unsigned long long fma2(unsigned long long a,
                                                   unsigned long long b,
                                                   unsigned long long c) {
    unsigned long long d;
    asm("fma.rn.f32x2 %0, %1, %2, %3;" : "=l"(d) : "l"(a), "l"(b), "l"(c));
    return d;
}
__device__ __forceinline__ unsigned long long mul2(unsigned long long a,
                                                   unsigned long long b) {
    unsigned long long d;
    asm("mul.rn.f32x2 %0, %1, %2;" : "=l"(d) : "l"(a), "l"(b));
    return d;
}
__device__ __forceinline__ unsigned long long pack2(float x) {
    unsigned long long d;
    asm("mov.b64 %0, {%1, %1};" : "=l"(d) : "f"(x));
    return d;
}
__device__ __forceinline__ float2 unpack2(unsigned long long v) {
    float2 f;
    asm("mov.b64 {%0, %1}, %2;" : "=f"(f.x), "=f"(f.y) : "l"(v));
    return f;
}

// ---------------- kernel 1: adj (int32, 256MB) -> bitmask (8MB) ----------------
__global__ __launch_bounds__(256) void mask_kernel(const int* __restrict__ adj) {
    int widx = blockIdx.x * 8 + (threadIdx.x >> 5);
    int lane = threadIdx.x & 31;
    int v = adj[(long long)widx * 32 + lane];
    unsigned b = __ballot_sync(0xffffffffu, v > 0);
    if (lane == 0) g_mask[widx] = b;
}

// ---------------- kernel 2: Wh = x @ W  (+ fused f1/f2) ----------------
// grid (64, 8): 128-row block x head.  256 threads.
// Thread tile: 4 rows x 8 dims, f32x2 accumulators.
__global__ __launch_bounds__(256, 2) void gemm_wh_kernel(
    const float* __restrict__ x, const float* __restrict__ W,
    const float* __restrict__ a1, const float* __restrict__ a2)
{
    __shared__ float As[16 * 128];   // [k][m]
    __shared__ float Bs[16 * 64];    // [k][d]
    const int h    = blockIdx.y;
    const int row0 = blockIdx.x * 128;
    const int t    = threadIdx.x;
    const int dg   = t & 7;          // dim group: dims dg*8 .. dg*8+7
    const int rg   = t >> 3;         // row group: rows rg*4 .. rg*4+3
    const float* Wb = W + h * (DIN * DOUT);

    unsigned long long acc[4][4];
#pragma unroll
    for (int r = 0; r < 4; ++r)
#pragma unroll
        for (int q = 0; q < 4; ++q) acc[r][q] = 0ull;

    for (int kt = 0; kt < 32; ++kt) {   // 512 / 16
        __syncthreads();
        // load A tile 128x16 (store k-major)
#pragma unroll
        for (int s2 = 0; s2 < 2; ++s2) {
            int idx = t + s2 * 256;
            int row = idx >> 2, kq = idx & 3;
            float4 v = ((const float4*)x)[(long long)(row0 + row) * 128 + kt * 4 + kq];
            As[(kq * 4 + 0) * 128 + row] = v.x;
            As[(kq * 4 + 1) * 128 + row] = v.y;
            As[(kq * 4 + 2) * 128 + row] = v.z;
            As[(kq * 4 + 3) * 128 + row] = v.w;
        }
        // load B tile 16x64
        {
            int k = t >> 4, dq = t & 15;
            ((float4*)Bs)[k * 16 + dq] = ((const float4*)Wb)[(kt * 16 + k) * 16 + dq];
        }
        __syncthreads();
#pragma unroll
        for (int k = 0; k < 16; ++k) {
            float4 av = *(const float4*)&As[k * 128 + rg * 4];
            const unsigned long long* bp =
                (const unsigned long long*)&Bs[k * 64 + dg * 8];
            unsigned long long b0 = bp[0], b1 = bp[1], b2 = bp[2], b3 = bp[3];
            unsigned long long p;
            p = pack2(av.x);
            acc[0][0] = fma2(p, b0, acc[0][0]); acc[0][1] = fma2(p, b1, acc[0][1]);
            acc[0][2] = fma2(p, b2, acc[0][2]); acc[0][3] = fma2(p, b3, acc[0][3]);
            p = pack2(av.y);
            acc[1][0] = fma2(p, b0, acc[1][0]); acc[1][1] = fma2(p, b1, acc[1][1]);
            acc[1][2] = fma2(p, b2, acc[1][2]); acc[1][3] = fma2(p, b3, acc[1][3]);
            p = pack2(av.z);
            acc[2][0] = fma2(p, b0, acc[2][0]); acc[2][1] = fma2(p, b1, acc[2][1]);
            acc[2][2] = fma2(p, b2, acc[2][2]); acc[2][3] = fma2(p, b3, acc[2][3]);
            p = pack2(av.w);
            acc[3][0] = fma2(p, b0, acc[3][0]); acc[3][1] = fma2(p, b1, acc[3][1]);
            acc[3][2] = fma2(p, b2, acc[3][2]); acc[3][3] = fma2(p, b3, acc[3][3]);
        }
    }

    // epilogue: write Wh, fused f1/f2
    float a1r[8], a2r[8];
#pragma unroll
    for (int q = 0; q < 8; ++q) {
        a1r[q] = a1[h * 64 + dg * 8 + q];
        a2r[q] = a2[h * 64 + dg * 8 + q];
    }
#pragma unroll
    for (int r = 0; r < 4; ++r) {
        int gi = row0 + rg * 4 + r;
        float vals[8];
#pragma unroll
        for (int q = 0; q < 4; ++q) {
            float2 f = unpack2(acc[r][q]);
            vals[2 * q] = f.x; vals[2 * q + 1] = f.y;
        }
        float4 o0 = make_float4(vals[0], vals[1], vals[2], vals[3]);
        float4 o1 = make_float4(vals[4], vals[5], vals[6], vals[7]);
        ((float4*)g_Wh)[(long long)gi * 128 + h * 16 + dg * 2]     = o0;
        ((float4*)g_Wh)[(long long)gi * 128 + h * 16 + dg * 2 + 1] = o1;
        float s1 = 0.f, s2v = 0.f;
#pragma unroll
        for (int q = 0; q < 8; ++q) { s1 += vals[q] * a1r[q]; s2v += vals[q] * a2r[q]; }
#pragma unroll
        for (int d = 4; d; d >>= 1) {
            s1  += __shfl_down_sync(0xffffffffu, s1,  d, 8);
            s2v += __shfl_down_sync(0xffffffffu, s2v, d, 8);
        }
        if (dg == 0) {
            g_f1[h * NN + gi] = s1;
            g_f2[h * NN + gi] = s2v;
        }
    }
}

// ---------------- kernel 3: fused masked-softmax attention ----------------
// grid (64, 8): 128-row block x head. 256 threads.
// Per 64-col tile: phase2 computes online-softmax probs (one exp per (i,j)),
// phase3 does acc += P @ Wh_tile with f32x2 register tiles (4 rows x 8 dims).
#define SM_WH   0       // 64*64
#define SM_PS   4096    // 128*65 (padded)
#define SM_F2   12416   // 64
#define SM_F1   12480   // 128
#define SM_M    12608   // 128
#define SM_L    12736   // 128
#define SM_SCL  12864   // 128
#define SM_MASK 12992   // 256 words
#define SM_FLOATS 13248

__global__ __launch_bounds__(256, 2) void attn_kernel(float* __restrict__ out) {
    extern __shared__ float sm[];
    float*    WhS   = sm + SM_WH;
    float*    Ps    = sm + SM_PS;   // [j][i] would conflict; layout [i][65]
    float*    f2s   = sm + SM_F2;
    float*    f1s   = sm + SM_F1;
    float*    mS    = sm + SM_M;
    float*    lS    = sm + SM_L;
    float*    sclS  = sm + SM_SCL;
    unsigned* maskS = (unsigned*)(sm + SM_MASK);

    const int h    = blockIdx.y;
    const int row0 = blockIdx.x * 128;
    const int t    = threadIdx.x;
    const int lane = t & 31, warp = t >> 5;
    const int dg   = t & 7;   // dims dg*8..+7
    const int rg   = t >> 3;  // rows rg*4..+3
    const float NEG_INF = __int_as_float(0xff800000);

    if (t < 128) {
        f1s[t] = g_f1[h * NN + row0 + t];
        mS[t]  = NEG_INF;
        lS[t]  = 0.f;
    }
    unsigned long long acc[4][4];
#pragma unroll
    for (int r = 0; r < 4; ++r)
#pragma unroll
        for (int q = 0; q < 4; ++q) acc[r][q] = 0ull;

    for (int jt = 0; jt < 128; ++jt) {    // 8192 / 64 col tiles
        const int j0 = jt * 64;
        __syncthreads();  // prev phase3 (and init) done before overwriting tiles
        // ---- loads ----
        if (t < 64) f2s[t] = g_f2[h * NN + j0 + t];
        maskS[t] = g_mask[(long long)(row0 + (t >> 1)) * MWORDS + jt * 2 + (t & 1)];
#pragma unroll
        for (int s2 = 0; s2 < 4; ++s2) {
            int idx = t + s2 * 256;
            int j = idx >> 4, dq = idx & 15;
            ((float4*)WhS)[j * 16 + dq] =
                ((const float4*)g_Wh)[(long long)(j0 + j) * 128 + h * 16 + dq];
        }
        __syncthreads();

        // ---- phase 2: scores + online softmax (warp per row, 16 rows/warp) ----
#pragma unroll 2
        for (int r = 0; r < 16; ++r) {
            int i = warp * 16 + r;
            float f1v = f1s[i];
            unsigned mw0 = maskS[i * 2], mw1 = maskS[i * 2 + 1];
            float e0 = f1v + f2s[lane];
            float e1 = f1v + f2s[lane + 32];
            e0 = e0 > 0.f ? e0 : 0.2f * e0;
            e1 = e1 > 0.f ? e1 : 0.2f * e1;
            bool k0 = (mw0 >> lane) & 1u;
            bool k1 = (mw1 >> lane) & 1u;
            float v0 = k0 ? e0 : NEG_INF;
            float v1 = k1 ? e1 : NEG_INF;
            float mx = fmaxf(v0, v1);
#pragma unroll
            for (int s = 16; s; s >>= 1)
                mx = fmaxf(mx, __shfl_xor_sync(0xffffffffu, mx, s));
            float m_old = mS[i];
            float m_new = fmaxf(m_old, mx);
            float p0 = 0.f, p1 = 0.f;
            if (m_new > NEG_INF) {
                p0 = k0 ? __expf(e0 - m_new) : 0.f;
                p1 = k1 ? __expf(e1 - m_new) : 0.f;
                float sum = p0 + p1;
#pragma unroll
                for (int s = 16; s; s >>= 1)
                    sum += __shfl_xor_sync(0xffffffffu, sum, s);
                float scl = __expf(m_old - m_new);   // exp(-inf)=0 handles first hit
                if (lane == 0) {
                    mS[i] = m_new;
                    lS[i] = lS[i] * scl + sum;
                    sclS[i] = scl;
                }
            } else {
                if (lane == 0) sclS[i] = 1.f;
            }
            Ps[i * 65 + lane]      = p0;
            Ps[i * 65 + lane + 32] = p1;
        }
        __syncthreads();

        // ---- phase 3: acc = acc*scale + P @ Wh_tile ----
#pragma unroll
        for (int r = 0; r < 4; ++r) {
            float s = sclS[rg * 4 + r];
            if (s != 1.f) {
                unsigned long long sp = pack2(s);
#pragma unroll
                for (int q = 0; q < 4; ++q) acc[r][q] = mul2(acc[r][q], sp);
            }
        }
#pragma unroll 4
        for (int j = 0; j < 64; ++j) {
            const unsigned long long* wp =
                (const unsigned long long*)&WhS[j * 64 + dg * 8];
            unsigned long long w0 = wp[0], w1 = wp[1], w2 = wp[2], w3 = wp[3];
#pragma unroll
            for (int r = 0; r < 4; ++r) {
                unsigned long long pp = pack2(Ps[(rg * 4 + r) * 65 + j]);
                acc[r][0] = fma2(pp, w0, acc[r][0]);
                acc[r][1] = fma2(pp, w1, acc[r][1]);
                acc[r][2] = fma2(pp, w2, acc[r][2]);
                acc[r][3] = fma2(pp, w3, acc[r][3]);
            }
        }
    }

    // ---- epilogue: normalize and write out[N][H*64] ----
#pragma unroll
    for (int r = 0; r < 4; ++r) {
        int i = rg * 4 + r;
        int gi = row0 + i;
        float inv = 1.0f / lS[i];
        float vals[8];
#pragma unroll
        for (int q = 0; q < 4; ++q) {
            float2 f = unpack2(acc[r][q]);
            vals[2 * q] = f.x * inv; vals[2 * q + 1] = f.y * inv;
        }
        float4 o0 = make_float4(vals[0], vals[1], vals[2], vals[3]);
        float4 o1 = make_float4(vals[4], vals[5], vals[6], vals[7]);
        ((float4*)out)[(long long)gi * 128 + h * 16 + dg * 2]     = o0;
        ((float4*)out)[(long long)gi * 128 + h * 16 + dg * 2 + 1] = o1;
    }
}

// ---------------- launch ----------------
extern "C" void kernel_launch(void* const* d_in, const int* in_sizes, int n_in,
                              void* d_out, int out_size) {
    const float* x   = (const float*)d_in[0];
    const int*   adj = (const int*)d_in[1];
    const float* W   = (const float*)d_in[2];
    const float* a1  = (const float*)d_in[3];
    const float* a2  = (const float*)d_in[4];
    float* out = (float*)d_out;

    mask_kernel<<<(NN * MWORDS) / 8, 256>>>(adj);
    gemm_wh_kernel<<<dim3(NN / 128, HEADS), 256>>>(x, W, a1, a2);

    cudaFuncSetAttribute(attn_kernel,
                         cudaFuncAttributeMaxDynamicSharedMemorySize,
                         SM_FLOATS * (int)sizeof(float));
    attn_kernel<<<dim3(NN / 128, HEADS), 256, SM_FLOATS * (int)sizeof(float)>>>(out);
}

// round 2
// speedup vs baseline: 4.7003x; 4.7003x over previous
#include <cuda_runtime.h>

// Problem constants
#define NN 8192
#define DIN 512
#define DOUT 64
#define HEADS 8
#define MWORDS 256       // 8192/32 mask words per row

// Scratch (device globals)
__device__ float    g_Wh[NN * 512];          // [N][H*64] fp32
__device__ float    g_f1[HEADS * NN];
__device__ float    g_f2[HEADS * NN];
__device__ float    g_f2max[HEADS];
__device__ unsigned g_mask[NN * MWORDS];     // 8 MB bitmask

// ---------------- packed f32x2 helpers ----------------
__device__ __forceinline__ unsigned long long fma2(unsigned long long a,
                                                   unsigned long long b,
                                                   unsigned long long c) {
    unsigned long long d;
    asm("fma.rn.f32x2 %0, %1, %2, %3;" : "=l"(d) : "l"(a), "l"(b), "l"(c));
    return d;
}
__device__ __forceinline__ unsigned long long pack2(float x) {
    unsigned long long d;
    asm("mov.b64 %0, {%1, %1};" : "=l"(d) : "f"(x));
    return d;
}
__device__ __forceinline__ float2 unpack2(unsigned long long v) {
    float2 f;
    asm("mov.b64 {%0, %1}, %2;" : "=f"(f.x), "=f"(f.y) : "l"(v));
    return f;
}
// tf32 round-to-nearest (result: fp32 bits with low 13 mantissa bits zero)
__device__ __forceinline__ unsigned tf32r(float x) {
    unsigned r;
    asm("cvt.rna.tf32.f32 %0, %1;" : "=r"(r) : "f"(x));
    return r;
}
__device__ __forceinline__ void mma_tf32(float c[4], unsigned a0, unsigned a1,
                                         unsigned a2, unsigned a3,
                                         unsigned b0, unsigned b1) {
    asm volatile(
        "mma.sync.aligned.m16n8k8.row.col.f32.tf32.tf32.f32 "
        "{%0,%1,%2,%3}, {%4,%5,%6,%7}, {%8,%9}, {%0,%1,%2,%3};"
        : "+f"(c[0]), "+f"(c[1]), "+f"(c[2]), "+f"(c[3])
        : "r"(a0), "r"(a1), "r"(a2), "r"(a3), "r"(b0), "r"(b1));
}

// ---------------- kernel 1: adj -> bitmask (MLP-8 unrolled) ----------------
__global__ __launch_bounds__(256) void mask_kernel(const int* __restrict__ adj) {
    const int UN = 8;
    long long w0 = ((long long)blockIdx.x * 8 + (threadIdx.x >> 5)) * UN;
    int lane = threadIdx.x & 31;
    int v[UN];
#pragma unroll
    for (int u = 0; u < UN; ++u) v[u] = adj[(w0 + u) * 32 + lane];
#pragma unroll
    for (int u = 0; u < UN; ++u) {
        unsigned b = __ballot_sync(0xffffffffu, v[u] > 0);
        if (lane == 0) g_mask[w0 + u] = b;
    }
}

// ---------------- kernel 2: Wh = x @ W (+ fused f1/f2) ----------------
__global__ __launch_bounds__(256, 2) void gemm_wh_kernel(
    const float* __restrict__ x, const float* __restrict__ W,
    const float* __restrict__ a1, const float* __restrict__ a2)
{
    __shared__ float As[16 * 128];
    __shared__ float Bs[16 * 64];
    const int h    = blockIdx.y;
    const int row0 = blockIdx.x * 128;
    const int t    = threadIdx.x;
    const int dg   = t & 7;
    const int rg   = t >> 3;
    const float* Wb = W + h * (DIN * DOUT);

    unsigned long long acc[4][4];
#pragma unroll
    for (int r = 0; r < 4; ++r)
#pragma unroll
        for (int q = 0; q < 4; ++q) acc[r][q] = 0ull;

    for (int kt = 0; kt < 32; ++kt) {
        __syncthreads();
#pragma unroll
        for (int s2 = 0; s2 < 2; ++s2) {
            int idx = t + s2 * 256;
            int row = idx >> 2, kq = idx & 3;
            float4 v = ((const float4*)x)[(long long)(row0 + row) * 128 + kt * 4 + kq];
            As[(kq * 4 + 0) * 128 + row] = v.x;
            As[(kq * 4 + 1) * 128 + row] = v.y;
            As[(kq * 4 + 2) * 128 + row] = v.z;
            As[(kq * 4 + 3) * 128 + row] = v.w;
        }
        {
            int k = t >> 4, dq = t & 15;
            ((float4*)Bs)[k * 16 + dq] = ((const float4*)Wb)[(kt * 16 + k) * 16 + dq];
        }
        __syncthreads();
#pragma unroll
        for (int k = 0; k < 16; ++k) {
            float4 av = *(const float4*)&As[k * 128 + rg * 4];
            const unsigned long long* bp =
                (const unsigned long long*)&Bs[k * 64 + dg * 8];
            unsigned long long b0 = bp[0], b1 = bp[1], b2 = bp[2], b3 = bp[3];
            unsigned long long p;
            p = pack2(av.x);
            acc[0][0] = fma2(p, b0, acc[0][0]); acc[0][1] = fma2(p, b1, acc[0][1]);
            acc[0][2] = fma2(p, b2, acc[0][2]); acc[0][3] = fma2(p, b3, acc[0][3]);
            p = pack2(av.y);
            acc[1][0] = fma2(p, b0, acc[1][0]); acc[1][1] = fma2(p, b1, acc[1][1]);
            acc[1][2] = fma2(p, b2, acc[1][2]); acc[1][3] = fma2(p, b3, acc[1][3]);
            p = pack2(av.z);
            acc[2][0] = fma2(p, b0, acc[2][0]); acc[2][1] = fma2(p, b1, acc[2][1]);
            acc[2][2] = fma2(p, b2, acc[2][2]); acc[2][3] = fma2(p, b3, acc[2][3]);
            p = pack2(av.w);
            acc[3][0] = fma2(p, b0, acc[3][0]); acc[3][1] = fma2(p, b1, acc[3][1]);
            acc[3][2] = fma2(p, b2, acc[3][2]); acc[3][3] = fma2(p, b3, acc[3][3]);
        }
    }

    float a1r[8], a2r[8];
#pragma unroll
    for (int q = 0; q < 8; ++q) {
        a1r[q] = a1[h * 64 + dg * 8 + q];
        a2r[q] = a2[h * 64 + dg * 8 + q];
    }
#pragma unroll
    for (int r = 0; r < 4; ++r) {
        int gi = row0 + rg * 4 + r;
        float vals[8];
#pragma unroll
        for (int q = 0; q < 4; ++q) {
            float2 f = unpack2(acc[r][q]);
            vals[2 * q] = f.x; vals[2 * q + 1] = f.y;
        }
        float4 o0 = make_float4(vals[0], vals[1], vals[2], vals[3]);
        float4 o1 = make_float4(vals[4], vals[5], vals[6], vals[7]);
        ((float4*)g_Wh)[(long long)gi * 128 + h * 16 + dg * 2]     = o0;
        ((float4*)g_Wh)[(long long)gi * 128 + h * 16 + dg * 2 + 1] = o1;
        float s1 = 0.f, s2v = 0.f;
#pragma unroll
        for (int q = 0; q < 8; ++q) { s1 += vals[q] * a1r[q]; s2v += vals[q] * a2r[q]; }
#pragma unroll
        for (int d = 4; d; d >>= 1) {
            s1  += __shfl_down_sync(0xffffffffu, s1,  d, 8);
            s2v += __shfl_down_sync(0xffffffffu, s2v, d, 8);
        }
        if (dg == 0) {
            g_f1[h * NN + gi] = s1;
            g_f2[h * NN + gi] = s2v;
        }
    }
}

// ---------------- kernel 2b: per-head max of f2 ----------------
__global__ __launch_bounds__(256) void f2max_kernel() {
    __shared__ float red[8];
    int h = blockIdx.x;
    float m = -3.4e38f;
    for (int i = threadIdx.x; i < NN; i += 256)
        m = fmaxf(m, g_f2[h * NN + i]);
#pragma unroll
    for (int s = 16; s; s >>= 1)
        m = fmaxf(m, __shfl_xor_sync(0xffffffffu, m, s));
    if ((threadIdx.x & 31) == 0) red[threadIdx.x >> 5] = m;
    __syncthreads();
    if (threadIdx.x < 8) {
        m = red[threadIdx.x];
#pragma unroll
        for (int s = 4; s; s >>= 1)
            m = fmaxf(m, __shfl_xor_sync(0x000000ffu, m, s));
        if (threadIdx.x == 0) g_f2max[h] = m;
    }
}

// ---------------- kernel 3: attention via tf32 mma ----------------
// grid (64, 8): 128-row block x head, 256 threads (8 warps x 16 rows).
// No online softmax: m_i = lrelu(f1_i + f2max) is a valid row max bound
// (e is monotone in f2). P fragments computed directly in registers.
#define WH_STRIDE 72   // 64 + 8 pad: conflict-free B-fragment LDS
__global__ __launch_bounds__(256, 2) void attn_kernel(float* __restrict__ out) {
    __shared__ float    WhS[64 * WH_STRIDE];
    __shared__ float    f2s[64];
    __shared__ unsigned maskS[256];

    const int h    = blockIdx.y;
    const int row0 = blockIdx.x * 128;
    const int t    = threadIdx.x;
    const int lane = t & 31, warp = t >> 5;
    const int gid  = lane >> 2, tig = lane & 3;
    const int r0   = warp * 16 + gid, r1 = r0 + 8;
    const long long gr0 = row0 + r0, gr1 = row0 + r1;

    const float f2max = g_f2max[h];
    const float f1a = g_f1[h * NN + gr0];
    const float f1b = g_f1[h * NN + gr1];
    float ea = f1a + f2max, eb = f1b + f2max;
    const float m0 = fmaxf(ea, 0.2f * ea);
    const float m1 = fmaxf(eb, 0.2f * eb);
    float l0 = 0.f, l1 = 0.f;

    float acc[8][4];
#pragma unroll
    for (int nc = 0; nc < 8; ++nc)
#pragma unroll
        for (int q = 0; q < 4; ++q) acc[nc][q] = 0.f;

    for (int jt = 0; jt < 128; ++jt) {
        const int j0 = jt * 64;
        __syncthreads();
        if (t < 64) f2s[t] = g_f2[h * NN + j0 + t];
        maskS[t] = g_mask[(long long)(row0 + (t >> 1)) * MWORDS + jt * 2 + (t & 1)];
#pragma unroll
        for (int s = 0; s < 4; ++s) {
            int idx = t + s * 256;         // 0..1023
            int j = idx >> 4, dq = idx & 15;
            float4 v = ((const float4*)g_Wh)[(long long)(j0 + j) * 128 + h * 16 + dq];
            float* dst = &WhS[j * WH_STRIDE + dq * 4];
            dst[0] = __uint_as_float(tf32r(v.x));
            dst[1] = __uint_as_float(tf32r(v.y));
            dst[2] = __uint_as_float(tf32r(v.z));
            dst[3] = __uint_as_float(tf32r(v.w));
        }
        __syncthreads();

        const unsigned mr0a = maskS[r0 * 2], mr0b = maskS[r0 * 2 + 1];
        const unsigned mr1a = maskS[r1 * 2], mr1b = maskS[r1 * 2 + 1];

#pragma unroll
        for (int kc = 0; kc < 8; ++kc) {
            const int k0 = kc * 8 + tig;     // k col in tile
            const int k1 = k0 + 4;
            const float f2x = f2s[k0], f2y = f2s[k1];
            float e, p0f, p1f, p2f, p3f;
            e = f1a + f2x; e = fmaxf(e, 0.2f * e); p0f = __expf(e - m0);
            e = f1b + f2x; e = fmaxf(e, 0.2f * e); p1f = __expf(e - m1);
            e = f1a + f2y; e = fmaxf(e, 0.2f * e); p2f = __expf(e - m0);
            e = f1b + f2y; e = fmaxf(e, 0.2f * e); p3f = __expf(e - m1);
            const unsigned w0 = (kc < 4) ? mr0a : mr0b;
            const unsigned w1 = (kc < 4) ? mr1a : mr1b;
            const int b0 = k0 & 31, b1 = k1 & 31;
            if (!((w0 >> b0) & 1u)) p0f = 0.f;
            if (!((w1 >> b0) & 1u)) p1f = 0.f;
            if (!((w0 >> b1) & 1u)) p2f = 0.f;
            if (!((w1 >> b1) & 1u)) p3f = 0.f;
            const unsigned a0 = tf32r(p0f), a1 = tf32r(p1f);
            const unsigned a2 = tf32r(p2f), a3 = tf32r(p3f);
            // denominator uses the SAME rounded weights as the mma numerator
            l0 += __uint_as_float(a0) + __uint_as_float(a2);
            l1 += __uint_as_float(a1) + __uint_as_float(a3);
#pragma unroll
            for (int nc = 0; nc < 8; ++nc) {
                const unsigned bb0 =
                    __float_as_uint(WhS[k0 * WH_STRIDE + nc * 8 + gid]);
                const unsigned bb1 =
                    __float_as_uint(WhS[k1 * WH_STRIDE + nc * 8 + gid]);
                mma_tf32(acc[nc], a0, a1, a2, a3, bb0, bb1);
            }
        }
    }

    // reduce l across the 4 threads sharing each row (quad)
    l0 += __shfl_xor_sync(0xffffffffu, l0, 1);
    l0 += __shfl_xor_sync(0xffffffffu, l0, 2);
    l1 += __shfl_xor_sync(0xffffffffu, l1, 1);
    l1 += __shfl_xor_sync(0xffffffffu, l1, 2);
    const float inv0 = 1.0f / l0, inv1 = 1.0f / l1;

#pragma unroll
    for (int nc = 0; nc < 8; ++nc) {
        const int col = h * 64 + nc * 8 + tig * 2;
        ((float2*)out)[(gr0 * 512 + col) >> 1] =
            make_float2(acc[nc][0] * inv0, acc[nc][1] * inv0);
        ((float2*)out)[(gr1 * 512 + col) >> 1] =
            make_float2(acc[nc][2] * inv1, acc[nc][3] * inv1);
    }
}

// ---------------- launch ----------------
extern "C" void kernel_launch(void* const* d_in, const int* in_sizes, int n_in,
                              void* d_out, int out_size) {
    const float* x   = (const float*)d_in[0];
    const int*   adj = (const int*)d_in[1];
    const float* W   = (const float*)d_in[2];
    const float* a1  = (const float*)d_in[3];
    const float* a2  = (const float*)d_in[4];
    float* out = (float*)d_out;

    mask_kernel<<<(NN * MWORDS) / 64, 256>>>(adj);
    gemm_wh_kernel<<<dim3(NN / 128, HEADS), 256>>>(x, W, a1, a2);
    f2max_kernel<<<HEADS, 256>>>();
    attn_kernel<<<dim3(NN / 128, HEADS), 256>>>(out);
}